// round 1
// baseline (speedup 1.0000x reference)
#include <cuda_runtime.h>

#define Bb 32
#define Cc 256
#define Nn 4096
#define N8 512
#define EPSf 1e-5f

// Scratch (device globals — no allocation allowed)
__device__ float g_q[(size_t)Bb * N8 * Cc];     // (B, 512, 256)
__device__ float g_k[(size_t)Bb * N8 * Cc];     // (B, 512, 256)
__device__ float g_sim[(size_t)Bb * Cc * Cc];   // (B, 256, 256), becomes aff in-place
__device__ float g_pooled[Bb * Cc];
__device__ float g_s[Bb * Cc];

__device__ __forceinline__ float warpMax(float v) {
#pragma unroll
    for (int o = 16; o; o >>= 1) v = fmaxf(v, __shfl_xor_sync(0xffffffffu, v, o));
    return v;
}
__device__ __forceinline__ float warpSum(float v) {
#pragma unroll
    for (int o = 16; o; o >>= 1) v += __shfl_xor_sync(0xffffffffu, v, o);
    return v;
}

// ---------------------------------------------------------------------------
// pooled[b,c] = max_n x[b,c,n]
// ---------------------------------------------------------------------------
__global__ void pool_kernel(const float* __restrict__ x) {
    int row = blockIdx.x;  // b*Cc + c
    const float4* xr = (const float4*)(x + (size_t)row * Nn);
    float m = -3.0e38f;
    for (int i = threadIdx.x; i < Nn / 4; i += 256) {
        float4 v = xr[i];
        m = fmaxf(m, fmaxf(fmaxf(v.x, v.y), fmaxf(v.z, v.w)));
    }
    m = warpMax(m);
    __shared__ float sm[8];
    if ((threadIdx.x & 31) == 0) sm[threadIdx.x >> 5] = m;
    __syncthreads();
    if (threadIdx.x == 0) {
        float r = sm[0];
#pragma unroll
        for (int i = 1; i < 8; i++) r = fmaxf(r, sm[i]);
        g_pooled[row] = r;
    }
}

// ---------------------------------------------------------------------------
// s[b,c] = sigmoid( relu(pooled @ W1^T) @ W2^T )   W1:(32,256) W2:(256,32)
// ---------------------------------------------------------------------------
__global__ void se_kernel(const float* __restrict__ W1, const float* __restrict__ W2) {
    int b = blockIdx.x;
    int t = threadIdx.x;
    __shared__ float h[32];
    if (t < 32) {
        float acc = 0.f;
        const float* w = W1 + t * Cc;
        const float* p = g_pooled + b * Cc;
        for (int c = 0; c < Cc; c++) acc += w[c] * p[c];
        h[t] = fmaxf(acc, 0.f);
    }
    __syncthreads();
    float acc = 0.f;
    const float* w2 = W2 + t * 32;
#pragma unroll
    for (int j = 0; j < 32; j++) acc += w2[j] * h[j];
    g_s[b * Cc + t] = 1.f / (1.f + expf(-acc));
}

// ---------------------------------------------------------------------------
// GEMM "NT": out[b,q,c] = relu(BN( sum_n W[q,n] * x[b,c,n] ))
// M=512 (q), N=256 (c), K=4096. Tile 128x128x8, 256 thr, 8x8 micro.
// ---------------------------------------------------------------------------
__global__ __launch_bounds__(256, 2) void gemm_qk_kernel(
    const float* __restrict__ W, const float* __restrict__ x,
    const float* __restrict__ gg, const float* __restrict__ bbp,
    const float* __restrict__ mmp, const float* __restrict__ vvp, int sel) {
    __shared__ float As[8][128];
    __shared__ float Bs[8][128];
    int b = blockIdx.z;
    int m0 = blockIdx.y * 128;
    int n0 = blockIdx.x * 128;
    int tid = threadIdx.x;
    int lrow = tid >> 1;
    int lcol = (tid & 1) << 2;
    int tx = tid & 15, ty = tid >> 4;
    const float* Ap = W + (size_t)(m0 + lrow) * Nn + lcol;
    const float* Bp = x + ((size_t)b * Cc + n0 + lrow) * Nn + lcol;

    float acc[8][8];
#pragma unroll
    for (int i = 0; i < 8; i++)
#pragma unroll
        for (int j = 0; j < 8; j++) acc[i][j] = 0.f;

    float4 a4 = *(const float4*)Ap;
    float4 b4 = *(const float4*)Bp;

    for (int k0 = 0; k0 < Nn; k0 += 8) {
        __syncthreads();
        As[lcol + 0][lrow] = a4.x; As[lcol + 1][lrow] = a4.y;
        As[lcol + 2][lrow] = a4.z; As[lcol + 3][lrow] = a4.w;
        Bs[lcol + 0][lrow] = b4.x; Bs[lcol + 1][lrow] = b4.y;
        Bs[lcol + 2][lrow] = b4.z; Bs[lcol + 3][lrow] = b4.w;
        __syncthreads();
        if (k0 + 8 < Nn) {
            a4 = *(const float4*)(Ap + k0 + 8);
            b4 = *(const float4*)(Bp + k0 + 8);
        }
#pragma unroll
        for (int kk = 0; kk < 8; kk++) {
            float a[8], bv[8];
            *(float4*)&a[0]  = *(float4*)&As[kk][ty * 8];
            *(float4*)&a[4]  = *(float4*)&As[kk][ty * 8 + 4];
            *(float4*)&bv[0] = *(float4*)&Bs[kk][tx * 8];
            *(float4*)&bv[4] = *(float4*)&Bs[kk][tx * 8 + 4];
#pragma unroll
            for (int i = 0; i < 8; i++)
#pragma unroll
                for (int j = 0; j < 8; j++) acc[i][j] += a[i] * bv[j];
        }
    }

    float* out = sel ? g_k : g_q;
#pragma unroll
    for (int i = 0; i < 8; i++) {
        int q = m0 + ty * 8 + i;
        float inv = rsqrtf(vvp[q] + EPSf);
        float sc = gg[q] * inv;
        float sh = bbp[q] - mmp[q] * sc;
        float* op = out + ((size_t)b * N8 + q) * Cc + n0 + tx * 8;
        float4 r0, r1;
        r0.x = fmaxf(acc[i][0] * sc + sh, 0.f); r0.y = fmaxf(acc[i][1] * sc + sh, 0.f);
        r0.z = fmaxf(acc[i][2] * sc + sh, 0.f); r0.w = fmaxf(acc[i][3] * sc + sh, 0.f);
        r1.x = fmaxf(acc[i][4] * sc + sh, 0.f); r1.y = fmaxf(acc[i][5] * sc + sh, 0.f);
        r1.z = fmaxf(acc[i][6] * sc + sh, 0.f); r1.w = fmaxf(acc[i][7] * sc + sh, 0.f);
        *(float4*)op = r0;
        *(float4*)(op + 4) = r1;
    }
}

// ---------------------------------------------------------------------------
// sim[b,c,d] = sum_kk k[b,kk,c] * q[b,kk,d]   M=N=256, K=512
// Operands are K-strided / MN-contiguous -> load tiles directly, no transpose.
// ---------------------------------------------------------------------------
__global__ __launch_bounds__(256, 2) void gemm_sim_kernel() {
    __shared__ float Ks[8][128];
    __shared__ float Qs[8][128];
    int b = blockIdx.z;
    int c0 = blockIdx.y * 128;
    int d0 = blockIdx.x * 128;
    int tid = threadIdx.x;
    int r = tid >> 5;
    int col = (tid & 31) << 2;
    int tx = tid & 15, ty = tid >> 4;
    const float* Kp = g_k + ((size_t)b * N8 + r) * Cc + c0 + col;
    const float* Qp = g_q + ((size_t)b * N8 + r) * Cc + d0 + col;

    float acc[8][8];
#pragma unroll
    for (int i = 0; i < 8; i++)
#pragma unroll
        for (int j = 0; j < 8; j++) acc[i][j] = 0.f;

    float4 a4 = *(const float4*)Kp;
    float4 b4 = *(const float4*)Qp;

    for (int k0 = 0; k0 < N8; k0 += 8) {
        __syncthreads();
        *(float4*)&Ks[r][col] = a4;
        *(float4*)&Qs[r][col] = b4;
        __syncthreads();
        if (k0 + 8 < N8) {
            a4 = *(const float4*)(Kp + (size_t)(k0 + 8) * Cc);
            b4 = *(const float4*)(Qp + (size_t)(k0 + 8) * Cc);
        }
#pragma unroll
        for (int kk = 0; kk < 8; kk++) {
            float a[8], bv[8];
            *(float4*)&a[0]  = *(float4*)&Ks[kk][ty * 8];
            *(float4*)&a[4]  = *(float4*)&Ks[kk][ty * 8 + 4];
            *(float4*)&bv[0] = *(float4*)&Qs[kk][tx * 8];
            *(float4*)&bv[4] = *(float4*)&Qs[kk][tx * 8 + 4];
#pragma unroll
            for (int i = 0; i < 8; i++)
#pragma unroll
                for (int j = 0; j < 8; j++) acc[i][j] += a[i] * bv[j];
        }
    }
#pragma unroll
    for (int i = 0; i < 8; i++) {
        float* op = g_sim + ((size_t)b * Cc + c0 + ty * 8 + i) * Cc + d0 + tx * 8;
        *(float4*)op       = *(float4*)&acc[i][0];
        *(float4*)(op + 4) = *(float4*)&acc[i][4];
    }
}

// ---------------------------------------------------------------------------
// aff = softmax_d(max_d(sim) - sim) == softmax_d(-sim)  (shift invariant)
// In-place on g_sim, one block per row.
// ---------------------------------------------------------------------------
__global__ void softmax_kernel() {
    int row = blockIdx.x;  // b*Cc + c
    float* p = g_sim + (size_t)row * Cc;
    int t = threadIdx.x;
    float v = -p[t];
    __shared__ float sm[8];
    __shared__ float ss[8];
    float wm = warpMax(v);
    if ((t & 31) == 0) sm[t >> 5] = wm;
    __syncthreads();
    float bm = sm[0];
#pragma unroll
    for (int i = 1; i < 8; i++) bm = fmaxf(bm, sm[i]);
    float e = expf(v - bm);
    float ws = warpSum(e);
    if ((t & 31) == 0) ss[t >> 5] = ws;
    __syncthreads();
    float tot = 0.f;
#pragma unroll
    for (int i = 0; i < 8; i++) tot += ss[i];
    p[t] = e / tot;
}

// ---------------------------------------------------------------------------
// out[b,c,n] = alpha * sum_d aff[b,c,d] * (x[b,d,n]*s[b,d]) + x[b,c,n]
// M=256 (c), N=4096 (n), K=256 (d)
// ---------------------------------------------------------------------------
__global__ __launch_bounds__(256, 2) void gemm_out_kernel(
    const float* __restrict__ x, const float* __restrict__ alpha,
    float* __restrict__ out) {
    __shared__ float As[8][128];
    __shared__ float Bs[8][128];
    int b = blockIdx.z;
    int c0 = blockIdx.y * 128;
    int n0 = blockIdx.x * 128;
    int tid = threadIdx.x;
    int lrow = tid >> 1;
    int lcol = (tid & 1) << 2;
    int r = tid >> 5;
    int col = (tid & 31) << 2;
    int tx = tid & 15, ty = tid >> 4;
    const float* Apb = g_sim + ((size_t)b * Cc + c0 + lrow) * Cc + lcol;
    const float* Bpb = x + ((size_t)b * Cc + r) * Nn + n0 + col;

    float acc[8][8];
#pragma unroll
    for (int i = 0; i < 8; i++)
#pragma unroll
        for (int j = 0; j < 8; j++) acc[i][j] = 0.f;

    float4 a4 = *(const float4*)Apb;
    float4 b4 = *(const float4*)Bpb;
    float sv = g_s[b * Cc + r];

    for (int k0 = 0; k0 < Cc; k0 += 8) {
        __syncthreads();
        As[lcol + 0][lrow] = a4.x; As[lcol + 1][lrow] = a4.y;
        As[lcol + 2][lrow] = a4.z; As[lcol + 3][lrow] = a4.w;
        float4 bs;
        bs.x = b4.x * sv; bs.y = b4.y * sv; bs.z = b4.z * sv; bs.w = b4.w * sv;
        *(float4*)&Bs[r][col] = bs;
        __syncthreads();
        if (k0 + 8 < Cc) {
            a4 = *(const float4*)(Apb + k0 + 8);
            b4 = *(const float4*)(Bpb + (size_t)(k0 + 8) * Nn);
            sv = g_s[b * Cc + k0 + 8 + r];
        }
#pragma unroll
        for (int kk = 0; kk < 8; kk++) {
            float a[8], bv[8];
            *(float4*)&a[0]  = *(float4*)&As[kk][ty * 8];
            *(float4*)&a[4]  = *(float4*)&As[kk][ty * 8 + 4];
            *(float4*)&bv[0] = *(float4*)&Bs[kk][tx * 8];
            *(float4*)&bv[4] = *(float4*)&Bs[kk][tx * 8 + 4];
#pragma unroll
            for (int i = 0; i < 8; i++)
#pragma unroll
                for (int j = 0; j < 8; j++) acc[i][j] += a[i] * bv[j];
        }
    }

    float al = alpha[0];
#pragma unroll
    for (int i = 0; i < 8; i++) {
        int c = c0 + ty * 8 + i;
        size_t base = ((size_t)b * Cc + c) * Nn + n0 + tx * 8;
        float4 x0 = *(const float4*)(x + base);
        float4 x1 = *(const float4*)(x + base + 4);
        float4 r0, r1;
        r0.x = al * acc[i][0] + x0.x; r0.y = al * acc[i][1] + x0.y;
        r0.z = al * acc[i][2] + x0.z; r0.w = al * acc[i][3] + x0.w;
        r1.x = al * acc[i][4] + x1.x; r1.y = al * acc[i][5] + x1.y;
        r1.z = al * acc[i][6] + x1.z; r1.w = al * acc[i][7] + x1.w;
        *(float4*)(out + base)     = r0;
        *(float4*)(out + base + 4) = r1;
    }
}

// ---------------------------------------------------------------------------
extern "C" void kernel_launch(void* const* d_in, const int* in_sizes, int n_in,
                              void* d_out, int out_size) {
    const float* x    = (const float*)d_in[0];
    const float* Wq   = (const float*)d_in[1];
    const float* bn1g = (const float*)d_in[2];
    const float* bn1b = (const float*)d_in[3];
    const float* bn1m = (const float*)d_in[4];
    const float* bn1v = (const float*)d_in[5];
    const float* Wk   = (const float*)d_in[6];
    const float* bn2g = (const float*)d_in[7];
    const float* bn2b = (const float*)d_in[8];
    const float* bn2m = (const float*)d_in[9];
    const float* bn2v = (const float*)d_in[10];
    const float* W1   = (const float*)d_in[11];
    const float* W2   = (const float*)d_in[12];
    const float* alpha = (const float*)d_in[13];
    float* out = (float*)d_out;

    pool_kernel<<<Bb * Cc, 256>>>(x);
    se_kernel<<<Bb, 256>>>(W1, W2);

    dim3 g1(Cc / 128, N8 / 128, Bb);
    gemm_qk_kernel<<<g1, 256>>>(Wq, x, bn1g, bn1b, bn1m, bn1v, 0);
    gemm_qk_kernel<<<g1, 256>>>(Wk, x, bn2g, bn2b, bn2m, bn2v, 1);

    dim3 g2(Cc / 128, Cc / 128, Bb);
    gemm_sim_kernel<<<g2, 256>>>();

    softmax_kernel<<<Bb * Cc, 256>>>();

    dim3 g3(Nn / 128, Cc / 128, Bb);
    gemm_out_kernel<<<g3, 256>>>(x, alpha, out);
}

// round 2
// speedup vs baseline: 2.1575x; 2.1575x over previous
#include <cuda_runtime.h>
#include <cstdint>

#define Bb 32
#define Cc 256
#define Nn 4096
#define N8 512
#define EPSf 1e-5f

// Scratch (device globals — no allocation allowed)
__device__ float g_q[(size_t)Bb * N8 * Cc];     // (B, 512, 256)
__device__ float g_k[(size_t)Bb * N8 * Cc];     // (B, 512, 256)
__device__ float g_sim[(size_t)Bb * Cc * Cc];   // (B, 256, 256), becomes aff in-place
__device__ float g_pooled[Bb * Cc];
__device__ float g_s[Bb * Cc];

__device__ __forceinline__ float warpMax(float v) {
#pragma unroll
    for (int o = 16; o; o >>= 1) v = fmaxf(v, __shfl_xor_sync(0xffffffffu, v, o));
    return v;
}
__device__ __forceinline__ float warpSum(float v) {
#pragma unroll
    for (int o = 16; o; o >>= 1) v += __shfl_xor_sync(0xffffffffu, v, o);
    return v;
}

__device__ __forceinline__ void mma_tf32(float* c, const uint32_t* a, const uint32_t* b) {
    asm volatile(
        "mma.sync.aligned.m16n8k8.row.col.f32.tf32.tf32.f32 "
        "{%0,%1,%2,%3}, {%4,%5,%6,%7}, {%8,%9}, {%0,%1,%2,%3};\n"
        : "+f"(c[0]), "+f"(c[1]), "+f"(c[2]), "+f"(c[3])
        : "r"(a[0]), "r"(a[1]), "r"(a[2]), "r"(a[3]), "r"(b[0]), "r"(b[1]));
}
__device__ __forceinline__ uint32_t f2tf(float x) {
    uint32_t r; asm("cvt.rna.tf32.f32 %0, %1;" : "=r"(r) : "f"(x)); return r;
}
__device__ __forceinline__ void sts8(uint32_t* dst, float4 v0, float4 v1) {
    uint4 u0 = { f2tf(v0.x), f2tf(v0.y), f2tf(v0.z), f2tf(v0.w) };
    uint4 u1 = { f2tf(v1.x), f2tf(v1.y), f2tf(v1.z), f2tf(v1.w) };
    *(uint4*)dst = u0; *(uint4*)(dst + 4) = u1;
}

// ---------------------------------------------------------------------------
// pooled[b,c] = max_n x[b,c,n]
// ---------------------------------------------------------------------------
__global__ void pool_kernel(const float* __restrict__ x) {
    int row = blockIdx.x;  // b*Cc + c
    const float4* xr = (const float4*)(x + (size_t)row * Nn);
    float m = -3.0e38f;
    for (int i = threadIdx.x; i < Nn / 4; i += 256) {
        float4 v = xr[i];
        m = fmaxf(m, fmaxf(fmaxf(v.x, v.y), fmaxf(v.z, v.w)));
    }
    m = warpMax(m);
    __shared__ float sm[8];
    if ((threadIdx.x & 31) == 0) sm[threadIdx.x >> 5] = m;
    __syncthreads();
    if (threadIdx.x == 0) {
        float r = sm[0];
#pragma unroll
        for (int i = 1; i < 8; i++) r = fmaxf(r, sm[i]);
        g_pooled[row] = r;
    }
}

// ---------------------------------------------------------------------------
// s[b,c] = sigmoid( relu(pooled @ W1^T) @ W2^T )
// ---------------------------------------------------------------------------
__global__ void se_kernel(const float* __restrict__ W1, const float* __restrict__ W2) {
    int b = blockIdx.x;
    int t = threadIdx.x;
    __shared__ float h[32];
    if (t < 32) {
        float acc = 0.f;
        const float* w = W1 + t * Cc;
        const float* p = g_pooled + b * Cc;
        for (int c = 0; c < Cc; c++) acc += w[c] * p[c];
        h[t] = fmaxf(acc, 0.f);
    }
    __syncthreads();
    float acc = 0.f;
    const float* w2 = W2 + t * 32;
#pragma unroll
    for (int j = 0; j < 32; j++) acc += w2[j] * h[j];
    g_s[b * Cc + t] = 1.f / (1.f + expf(-acc));
}

// ---------------------------------------------------------------------------
// Tensor-core GEMM: out[b,q,c] = relu(BN( sum_n W[q,n]*x[b,c,n] ))
// M=512, N=256, K=4096. Block 128x128, kc=16, 8 warps of 64x32.
// Both operands K-contiguous. Smem row stride 20 -> conflict-free frag LDS.
// ---------------------------------------------------------------------------
__global__ __launch_bounds__(256) void gemm_qk_tc(
    const float* __restrict__ W, const float* __restrict__ x,
    const float* __restrict__ gg, const float* __restrict__ bbp,
    const float* __restrict__ mmp, const float* __restrict__ vvp, int sel) {
    __shared__ uint32_t As[2][128 * 20];
    __shared__ uint32_t Bs[2][128 * 20];
    const int b = blockIdx.z;
    const int m0 = blockIdx.y * 128;
    const int n0 = blockIdx.x * 128;
    const int tid = threadIdx.x;
    const int lane = tid & 31, warp = tid >> 5;
    const int wm = (warp >> 2) * 64, wn = (warp & 3) * 32;
    const int g = lane >> 2, t4 = lane & 3;

    const int sm = tid >> 1;
    const int skq = (tid & 1) << 3;
    const float* pA = W + (size_t)(m0 + sm) * Nn + skq;
    const float* pB = x + ((size_t)b * Cc + n0 + sm) * Nn + skq;

    float acc[4][4][4];
#pragma unroll
    for (int i = 0; i < 4; i++)
#pragma unroll
        for (int j = 0; j < 4; j++)
#pragma unroll
            for (int r = 0; r < 4; r++) acc[i][j][r] = 0.f;

    float4 ra0 = *(const float4*)pA;
    float4 ra1 = *(const float4*)(pA + 4);
    float4 rb0 = *(const float4*)pB;
    float4 rb1 = *(const float4*)(pB + 4);

    const int NC = Nn / 16;
    sts8(&As[0][sm * 20 + skq], ra0, ra1);
    sts8(&Bs[0][sm * 20 + skq], rb0, rb1);
    __syncthreads();

    for (int c = 0; c < NC; c++) {
        int buf = c & 1;
        if (c + 1 < NC) {
            const float* qA = pA + (size_t)(c + 1) * 16;
            const float* qB = pB + (size_t)(c + 1) * 16;
            ra0 = *(const float4*)qA; ra1 = *(const float4*)(qA + 4);
            rb0 = *(const float4*)qB; rb1 = *(const float4*)(qB + 4);
        }
        const uint32_t* Au = As[buf];
        const uint32_t* Bu = Bs[buf];
#pragma unroll
        for (int ks = 0; ks < 2; ks++) {
            uint32_t af[4][4], bfr[4][2];
#pragma unroll
            for (int mi = 0; mi < 4; mi++) {
                int r = wm + mi * 16 + g;
                int kk = ks * 8 + t4;
                af[mi][0] = Au[r * 20 + kk];
                af[mi][1] = Au[(r + 8) * 20 + kk];
                af[mi][2] = Au[r * 20 + kk + 4];
                af[mi][3] = Au[(r + 8) * 20 + kk + 4];
            }
#pragma unroll
            for (int ni = 0; ni < 4; ni++) {
                int cn = wn + ni * 8 + g;
                bfr[ni][0] = Bu[cn * 20 + ks * 8 + t4];
                bfr[ni][1] = Bu[cn * 20 + ks * 8 + t4 + 4];
            }
#pragma unroll
            for (int mi = 0; mi < 4; mi++)
#pragma unroll
                for (int ni = 0; ni < 4; ni++)
                    mma_tf32(acc[mi][ni], af[mi], bfr[ni]);
        }
        if (c + 1 < NC) {
            sts8(&As[buf ^ 1][sm * 20 + skq], ra0, ra1);
            sts8(&Bs[buf ^ 1][sm * 20 + skq], rb0, rb1);
        }
        __syncthreads();
    }

    float* outp = sel ? g_k : g_q;
#pragma unroll
    for (int mi = 0; mi < 4; mi++) {
        int r0 = m0 + wm + mi * 16 + g;
        int r1 = r0 + 8;
        float sc0 = gg[r0] * rsqrtf(vvp[r0] + EPSf);
        float sh0 = bbp[r0] - mmp[r0] * sc0;
        float sc1 = gg[r1] * rsqrtf(vvp[r1] + EPSf);
        float sh1 = bbp[r1] - mmp[r1] * sc1;
#pragma unroll
        for (int ni = 0; ni < 4; ni++) {
            int cn = n0 + wn + ni * 8 + 2 * t4;
            float2 v0, v1;
            v0.x = fmaxf(acc[mi][ni][0] * sc0 + sh0, 0.f);
            v0.y = fmaxf(acc[mi][ni][1] * sc0 + sh0, 0.f);
            v1.x = fmaxf(acc[mi][ni][2] * sc1 + sh1, 0.f);
            v1.y = fmaxf(acc[mi][ni][3] * sc1 + sh1, 0.f);
            *(float2*)&outp[((size_t)b * N8 + r0) * Cc + cn] = v0;
            *(float2*)&outp[((size_t)b * N8 + r1) * Cc + cn] = v1;
        }
    }
}

// ---------------------------------------------------------------------------
// sim[b,c,d] = sum_kk k[b,kk,c]*q[b,kk,d]  (FFMA, small: 2.15 GFLOP)
// ---------------------------------------------------------------------------
__global__ __launch_bounds__(256, 2) void gemm_sim_kernel() {
    __shared__ float Ks[8][128];
    __shared__ float Qs[8][128];
    int b = blockIdx.z;
    int c0 = blockIdx.y * 128;
    int d0 = blockIdx.x * 128;
    int tid = threadIdx.x;
    int r = tid >> 5;
    int col = (tid & 31) << 2;
    int tx = tid & 15, ty = tid >> 4;
    const float* Kp = g_k + ((size_t)b * N8 + r) * Cc + c0 + col;
    const float* Qp = g_q + ((size_t)b * N8 + r) * Cc + d0 + col;

    float acc[8][8];
#pragma unroll
    for (int i = 0; i < 8; i++)
#pragma unroll
        for (int j = 0; j < 8; j++) acc[i][j] = 0.f;

    float4 a4 = *(const float4*)Kp;
    float4 b4 = *(const float4*)Qp;

    for (int k0 = 0; k0 < N8; k0 += 8) {
        __syncthreads();
        *(float4*)&Ks[r][col] = a4;
        *(float4*)&Qs[r][col] = b4;
        __syncthreads();
        if (k0 + 8 < N8) {
            a4 = *(const float4*)(Kp + (size_t)(k0 + 8) * Cc);
            b4 = *(const float4*)(Qp + (size_t)(k0 + 8) * Cc);
        }
#pragma unroll
        for (int kk = 0; kk < 8; kk++) {
            float a[8], bv[8];
            *(float4*)&a[0]  = *(float4*)&Ks[kk][ty * 8];
            *(float4*)&a[4]  = *(float4*)&Ks[kk][ty * 8 + 4];
            *(float4*)&bv[0] = *(float4*)&Qs[kk][tx * 8];
            *(float4*)&bv[4] = *(float4*)&Qs[kk][tx * 8 + 4];
#pragma unroll
            for (int i = 0; i < 8; i++)
#pragma unroll
                for (int j = 0; j < 8; j++) acc[i][j] += a[i] * bv[j];
        }
    }
#pragma unroll
    for (int i = 0; i < 8; i++) {
        float* op = g_sim + ((size_t)b * Cc + c0 + ty * 8 + i) * Cc + d0 + tx * 8;
        *(float4*)op       = *(float4*)&acc[i][0];
        *(float4*)(op + 4) = *(float4*)&acc[i][4];
    }
}

// ---------------------------------------------------------------------------
// aff = softmax_d(-sim), in place
// ---------------------------------------------------------------------------
__global__ void softmax_kernel() {
    int row = blockIdx.x;
    float* p = g_sim + (size_t)row * Cc;
    int t = threadIdx.x;
    float v = -p[t];
    __shared__ float sm[8];
    __shared__ float ss[8];
    float wm = warpMax(v);
    if ((t & 31) == 0) sm[t >> 5] = wm;
    __syncthreads();
    float bm = sm[0];
#pragma unroll
    for (int i = 1; i < 8; i++) bm = fmaxf(bm, sm[i]);
    float e = expf(v - bm);
    float ws = warpSum(e);
    if ((t & 31) == 0) ss[t >> 5] = ws;
    __syncthreads();
    float tot = 0.f;
#pragma unroll
    for (int i = 0; i < 8; i++) tot += ss[i];
    p[t] = e / tot;
}

// ---------------------------------------------------------------------------
// Tensor-core GEMM: out[b,c,n] = alpha*sum_d aff[b,c,d]*(x[b,d,n]*s[b,d]) + x
// M=256 (c), N=4096 (n), K=256 (d). A K-contig; B transposed at staging.
// ---------------------------------------------------------------------------
__global__ __launch_bounds__(256) void gemm_out_tc(
    const float* __restrict__ x, const float* __restrict__ alpha,
    float* __restrict__ out) {
    __shared__ uint32_t As[2][128 * 20];
    __shared__ uint32_t Bs2[2][16 * 132];
    const int b = blockIdx.z;
    const int m0 = blockIdx.y * 128;
    const int n0 = blockIdx.x * 128;
    const int tid = threadIdx.x;
    const int lane = tid & 31, warp = tid >> 5;
    const int wm = (warp >> 2) * 64, wn = (warp & 3) * 32;
    const int g = lane >> 2, t4 = lane & 3;

    // A staging: thread -> (row, 8-k chunk)
    const int sm = tid >> 1;
    const int skq = (tid & 1) << 3;
    const float* pA = g_sim + ((size_t)b * Cc + m0 + sm) * Cc + skq;
    // B staging: thread -> (d, 8-n chunk)
    const int sd = tid >> 4;            // 0..15
    const int snq = (tid & 15) << 3;    // 0..120
    const float* pB = x + ((size_t)b * Cc + sd) * Nn + n0 + snq;
    const float* ps = g_s + b * Cc + sd;

    float acc[4][4][4];
#pragma unroll
    for (int i = 0; i < 4; i++)
#pragma unroll
        for (int j = 0; j < 4; j++)
#pragma unroll
            for (int r = 0; r < 4; r++) acc[i][j][r] = 0.f;

    float4 ra0 = *(const float4*)pA;
    float4 ra1 = *(const float4*)(pA + 4);
    float4 rb0 = *(const float4*)pB;
    float4 rb1 = *(const float4*)(pB + 4);
    float sv = *ps;

    const int NC = Cc / 16;  // 16 chunks

    // initial stage
    sts8(&As[0][sm * 20 + skq], ra0, ra1);
    {
        uint32_t* d = &Bs2[0][sd * 132 + snq];
        d[0] = f2tf(rb0.x * sv); d[1] = f2tf(rb0.y * sv);
        d[2] = f2tf(rb0.z * sv); d[3] = f2tf(rb0.w * sv);
        d[4] = f2tf(rb1.x * sv); d[5] = f2tf(rb1.y * sv);
        d[6] = f2tf(rb1.z * sv); d[7] = f2tf(rb1.w * sv);
    }
    __syncthreads();

    for (int c = 0; c < NC; c++) {
        int buf = c & 1;
        if (c + 1 < NC) {
            const float* qA = pA + (c + 1) * 16;
            ra0 = *(const float4*)qA; ra1 = *(const float4*)(qA + 4);
            const float* qB = pB + (size_t)(c + 1) * 16 * Nn;
            rb0 = *(const float4*)qB; rb1 = *(const float4*)(qB + 4);
            sv = ps[(c + 1) * 16];
        }
        const uint32_t* Au = As[buf];
        const uint32_t* Bu = Bs2[buf];
#pragma unroll
        for (int ks = 0; ks < 2; ks++) {
            uint32_t af[4][4], bfr[4][2];
#pragma unroll
            for (int mi = 0; mi < 4; mi++) {
                int r = wm + mi * 16 + g;
                int kk = ks * 8 + t4;
                af[mi][0] = Au[r * 20 + kk];
                af[mi][1] = Au[(r + 8) * 20 + kk];
                af[mi][2] = Au[r * 20 + kk + 4];
                af[mi][3] = Au[(r + 8) * 20 + kk + 4];
            }
#pragma unroll
            for (int ni = 0; ni < 4; ni++) {
                int cn = wn + ni * 8 + g;
                int kk = ks * 8 + t4;
                bfr[ni][0] = Bu[kk * 132 + cn];
                bfr[ni][1] = Bu[(kk + 4) * 132 + cn];
            }
#pragma unroll
            for (int mi = 0; mi < 4; mi++)
#pragma unroll
                for (int ni = 0; ni < 4; ni++)
                    mma_tf32(acc[mi][ni], af[mi], bfr[ni]);
        }
        if (c + 1 < NC) {
            sts8(&As[buf ^ 1][sm * 20 + skq], ra0, ra1);
            uint32_t* d = &Bs2[buf ^ 1][sd * 132 + snq];
            d[0] = f2tf(rb0.x * sv); d[1] = f2tf(rb0.y * sv);
            d[2] = f2tf(rb0.z * sv); d[3] = f2tf(rb0.w * sv);
            d[4] = f2tf(rb1.x * sv); d[5] = f2tf(rb1.y * sv);
            d[6] = f2tf(rb1.z * sv); d[7] = f2tf(rb1.w * sv);
        }
        __syncthreads();
    }

    float al = alpha[0];
#pragma unroll
    for (int mi = 0; mi < 4; mi++) {
        int r0 = m0 + wm + mi * 16 + g;
        int r1 = r0 + 8;
#pragma unroll
        for (int ni = 0; ni < 4; ni++) {
            int cn = n0 + wn + ni * 8 + 2 * t4;
            size_t a0 = ((size_t)b * Cc + r0) * Nn + cn;
            size_t a1 = ((size_t)b * Cc + r1) * Nn + cn;
            float2 x0 = *(const float2*)(x + a0);
            float2 x1 = *(const float2*)(x + a1);
            float2 v0, v1;
            v0.x = al * acc[mi][ni][0] + x0.x;
            v0.y = al * acc[mi][ni][1] + x0.y;
            v1.x = al * acc[mi][ni][2] + x1.x;
            v1.y = al * acc[mi][ni][3] + x1.y;
            *(float2*)(out + a0) = v0;
            *(float2*)(out + a1) = v1;
        }
    }
}

// ---------------------------------------------------------------------------
extern "C" void kernel_launch(void* const* d_in, const int* in_sizes, int n_in,
                              void* d_out, int out_size) {
    const float* x    = (const float*)d_in[0];
    const float* Wq   = (const float*)d_in[1];
    const float* bn1g = (const float*)d_in[2];
    const float* bn1b = (const float*)d_in[3];
    const float* bn1m = (const float*)d_in[4];
    const float* bn1v = (const float*)d_in[5];
    const float* Wk   = (const float*)d_in[6];
    const float* bn2g = (const float*)d_in[7];
    const float* bn2b = (const float*)d_in[8];
    const float* bn2m = (const float*)d_in[9];
    const float* bn2v = (const float*)d_in[10];
    const float* W1   = (const float*)d_in[11];
    const float* W2   = (const float*)d_in[12];
    const float* alpha = (const float*)d_in[13];
    float* out = (float*)d_out;

    pool_kernel<<<Bb * Cc, 256>>>(x);
    se_kernel<<<Bb, 256>>>(W1, W2);

    dim3 g1(Cc / 128, N8 / 128, Bb);
    gemm_qk_tc<<<g1, 256>>>(Wq, x, bn1g, bn1b, bn1m, bn1v, 0);
    gemm_qk_tc<<<g1, 256>>>(Wk, x, bn2g, bn2b, bn2m, bn2v, 1);

    dim3 g2(Cc / 128, Cc / 128, Bb);
    gemm_sim_kernel<<<g2, 256>>>();

    softmax_kernel<<<Bb * Cc, 256>>>();

    dim3 g3(Nn / 128, Cc / 128, Bb);
    gemm_out_tc<<<g3, 256>>>(x, alpha, out);
}

// round 3
// speedup vs baseline: 3.0675x; 1.4218x over previous
#include <cuda_runtime.h>
#include <cstdint>

#define Bb 32
#define Cc 256
#define Nn 4096
#define N8 512
#define EPSf 1e-5f

// Scratch (device globals — no allocation allowed)
__device__ float g_q[(size_t)Bb * N8 * Cc];
__device__ float g_k[(size_t)Bb * N8 * Cc];
__device__ float g_sim[(size_t)Bb * Cc * Cc];   // becomes alpha*aff*s in-place
__device__ float g_pooled[Bb * Cc];
__device__ float g_s[Bb * Cc];

__device__ __forceinline__ float warpMax(float v) {
#pragma unroll
    for (int o = 16; o; o >>= 1) v = fmaxf(v, __shfl_xor_sync(0xffffffffu, v, o));
    return v;
}
__device__ __forceinline__ float warpSum(float v) {
#pragma unroll
    for (int o = 16; o; o >>= 1) v += __shfl_xor_sync(0xffffffffu, v, o);
    return v;
}

__device__ __forceinline__ void mma_tf32(float* c, const uint32_t* a, const uint32_t* b) {
    asm volatile(
        "mma.sync.aligned.m16n8k8.row.col.f32.tf32.tf32.f32 "
        "{%0,%1,%2,%3}, {%4,%5,%6,%7}, {%8,%9}, {%0,%1,%2,%3};\n"
        : "+f"(c[0]), "+f"(c[1]), "+f"(c[2]), "+f"(c[3])
        : "r"(a[0]), "r"(a[1]), "r"(a[2]), "r"(a[3]), "r"(b[0]), "r"(b[1]));
}

__device__ __forceinline__ void cp16(void* s, const void* g) {
    uint32_t sa = (uint32_t)__cvta_generic_to_shared(s);
    asm volatile("cp.async.cg.shared.global [%0], [%1], 16;" :: "r"(sa), "l"(g));
}
#define CP_COMMIT() asm volatile("cp.async.commit_group;")
#define CP_WAIT2()  asm volatile("cp.async.wait_group 2;")

// ---------------------------------------------------------------------------
__global__ void pool_kernel(const float* __restrict__ x) {
    int row = blockIdx.x;
    const float4* xr = (const float4*)(x + (size_t)row * Nn);
    float m = -3.0e38f;
    for (int i = threadIdx.x; i < Nn / 4; i += 256) {
        float4 v = xr[i];
        m = fmaxf(m, fmaxf(fmaxf(v.x, v.y), fmaxf(v.z, v.w)));
    }
    m = warpMax(m);
    __shared__ float sm[8];
    if ((threadIdx.x & 31) == 0) sm[threadIdx.x >> 5] = m;
    __syncthreads();
    if (threadIdx.x == 0) {
        float r = sm[0];
#pragma unroll
        for (int i = 1; i < 8; i++) r = fmaxf(r, sm[i]);
        g_pooled[row] = r;
    }
}

// ---------------------------------------------------------------------------
__global__ void se_kernel(const float* __restrict__ W1, const float* __restrict__ W2) {
    int b = blockIdx.x;
    int t = threadIdx.x;
    __shared__ float h[32];
    if (t < 32) {
        float acc = 0.f;
        const float* w = W1 + t * Cc;
        const float* p = g_pooled + b * Cc;
        for (int c = 0; c < Cc; c++) acc += w[c] * p[c];
        h[t] = fmaxf(acc, 0.f);
    }
    __syncthreads();
    float acc = 0.f;
    const float* w2 = W2 + t * 32;
#pragma unroll
    for (int j = 0; j < 32; j++) acc += w2[j] * h[j];
    g_s[b * Cc + t] = 1.f / (1.f + expf(-acc));
}

// ---------------------------------------------------------------------------
// Fused q/k tensor-core GEMM, cp.async 4-stage pipeline.
// out[b,q,c] = relu(BN( sum_n W[q,n]*x[b,c,n] )). M=512,N=256,K=4096.
// Block 128x128, kc=16, 8 warps 64x32. grid.z encodes (b, sel).
// ---------------------------------------------------------------------------
#define QK_AS 2560   // 128*20 floats per stage
#define QK_PIPE 4

__global__ __launch_bounds__(256, 2) void gemm_qk_tc(
    const float* __restrict__ Wq, const float* __restrict__ Wk,
    const float* __restrict__ x,
    const float* __restrict__ gq, const float* __restrict__ bq,
    const float* __restrict__ mq, const float* __restrict__ vq,
    const float* __restrict__ gk, const float* __restrict__ bk,
    const float* __restrict__ mk, const float* __restrict__ vk) {
    extern __shared__ float smem[];
    float* Abuf = smem;                         // 4 stages of 128x20
    float* Bbuf = smem + QK_PIPE * QK_AS;       // 4 stages of 128x20

    const int z = blockIdx.z;
    const int b = z >> 1;
    const int sel = z & 1;
    const float* W = sel ? Wk : Wq;
    const int m0 = blockIdx.y * 128;
    const int n0 = blockIdx.x * 128;
    const int tid = threadIdx.x;
    const int lane = tid & 31, warp = tid >> 5;
    const int wm = (warp >> 2) * 64, wn = (warp & 3) * 32;
    const int g = lane >> 2, t4 = lane & 3;

    // cp.async mapping: thread -> (row r and r+64, 16B chunk q)
    const int r = tid >> 2;
    const int q = tid & 3;
    const float* gA0 = W + (size_t)(m0 + r) * Nn + q * 4;
    const float* gA1 = gA0 + (size_t)64 * Nn;
    const float* gB0 = x + ((size_t)b * Cc + n0 + r) * Nn + q * 4;
    const float* gB1 = gB0 + (size_t)64 * Nn;
    float* sA0 = Abuf + r * 20 + q * 4;
    float* sA1 = sA0 + 64 * 20;
    float* sB0 = Bbuf + r * 20 + q * 4;
    float* sB1 = sB0 + 64 * 20;

    const int NC = Nn / 16;  // 256

#pragma unroll
    for (int s = 0; s < QK_PIPE - 1; s++) {
        cp16(sA0 + s * QK_AS, gA0 + s * 16);
        cp16(sA1 + s * QK_AS, gA1 + s * 16);
        cp16(sB0 + s * QK_AS, gB0 + s * 16);
        cp16(sB1 + s * QK_AS, gB1 + s * 16);
        CP_COMMIT();
    }

    float acc[4][4][4];
#pragma unroll
    for (int i = 0; i < 4; i++)
#pragma unroll
        for (int j = 0; j < 4; j++)
#pragma unroll
            for (int rr = 0; rr < 4; rr++) acc[i][j][rr] = 0.f;

    for (int c = 0; c < NC; c++) {
        CP_WAIT2();
        __syncthreads();
        const uint32_t* Au = (const uint32_t*)(Abuf + (c % QK_PIPE) * QK_AS);
        const uint32_t* Bu = (const uint32_t*)(Bbuf + (c % QK_PIPE) * QK_AS);
#pragma unroll
        for (int ks = 0; ks < 2; ks++) {
            uint32_t af[4][4], bfr[4][2];
#pragma unroll
            for (int mi = 0; mi < 4; mi++) {
                int rw = wm + mi * 16 + g;
                int kk = ks * 8 + t4;
                af[mi][0] = Au[rw * 20 + kk];
                af[mi][1] = Au[(rw + 8) * 20 + kk];
                af[mi][2] = Au[rw * 20 + kk + 4];
                af[mi][3] = Au[(rw + 8) * 20 + kk + 4];
            }
#pragma unroll
            for (int ni = 0; ni < 4; ni++) {
                int cn = wn + ni * 8 + g;
                bfr[ni][0] = Bu[cn * 20 + ks * 8 + t4];
                bfr[ni][1] = Bu[cn * 20 + ks * 8 + t4 + 4];
            }
#pragma unroll
            for (int mi = 0; mi < 4; mi++)
#pragma unroll
                for (int ni = 0; ni < 4; ni++)
                    mma_tf32(acc[mi][ni], af[mi], bfr[ni]);
        }
        int nx = c + QK_PIPE - 1;
        if (nx < NC) {
            int s = nx % QK_PIPE;
            cp16(sA0 + s * QK_AS, gA0 + (size_t)nx * 16);
            cp16(sA1 + s * QK_AS, gA1 + (size_t)nx * 16);
            cp16(sB0 + s * QK_AS, gB0 + (size_t)nx * 16);
            cp16(sB1 + s * QK_AS, gB1 + (size_t)nx * 16);
        }
        CP_COMMIT();
        __syncthreads();
    }

    const float* gg = sel ? gk : gq;
    const float* bbp = sel ? bk : bq;
    const float* mmp = sel ? mk : mq;
    const float* vvp = sel ? vk : vq;
    float* outp = sel ? g_k : g_q;
#pragma unroll
    for (int mi = 0; mi < 4; mi++) {
        int r0 = m0 + wm + mi * 16 + g;
        int r1 = r0 + 8;
        float sc0 = gg[r0] * rsqrtf(vvp[r0] + EPSf);
        float sh0 = bbp[r0] - mmp[r0] * sc0;
        float sc1 = gg[r1] * rsqrtf(vvp[r1] + EPSf);
        float sh1 = bbp[r1] - mmp[r1] * sc1;
#pragma unroll
        for (int ni = 0; ni < 4; ni++) {
            int cn = n0 + wn + ni * 8 + 2 * t4;
            float2 v0, v1;
            v0.x = fmaxf(acc[mi][ni][0] * sc0 + sh0, 0.f);
            v0.y = fmaxf(acc[mi][ni][1] * sc0 + sh0, 0.f);
            v1.x = fmaxf(acc[mi][ni][2] * sc1 + sh1, 0.f);
            v1.y = fmaxf(acc[mi][ni][3] * sc1 + sh1, 0.f);
            *(float2*)&outp[((size_t)b * N8 + r0) * Cc + cn] = v0;
            *(float2*)&outp[((size_t)b * N8 + r1) * Cc + cn] = v1;
        }
    }
}

// ---------------------------------------------------------------------------
// sim[b,c,d] = sum_kk k[b,kk,c]*q[b,kk,d]  (FFMA, small)
// ---------------------------------------------------------------------------
__global__ __launch_bounds__(256, 2) void gemm_sim_kernel() {
    __shared__ float Ks[8][128];
    __shared__ float Qs[8][128];
    int b = blockIdx.z;
    int c0 = blockIdx.y * 128;
    int d0 = blockIdx.x * 128;
    int tid = threadIdx.x;
    int r = tid >> 5;
    int col = (tid & 31) << 2;
    int tx = tid & 15, ty = tid >> 4;
    const float* Kp = g_k + ((size_t)b * N8 + r) * Cc + c0 + col;
    const float* Qp = g_q + ((size_t)b * N8 + r) * Cc + d0 + col;

    float acc[8][8];
#pragma unroll
    for (int i = 0; i < 8; i++)
#pragma unroll
        for (int j = 0; j < 8; j++) acc[i][j] = 0.f;

    float4 a4 = *(const float4*)Kp;
    float4 b4 = *(const float4*)Qp;

    for (int k0 = 0; k0 < N8; k0 += 8) {
        __syncthreads();
        *(float4*)&Ks[r][col] = a4;
        *(float4*)&Qs[r][col] = b4;
        __syncthreads();
        if (k0 + 8 < N8) {
            a4 = *(const float4*)(Kp + (size_t)(k0 + 8) * Cc);
            b4 = *(const float4*)(Qp + (size_t)(k0 + 8) * Cc);
        }
#pragma unroll
        for (int kk = 0; kk < 8; kk++) {
            float a[8], bv[8];
            *(float4*)&a[0]  = *(float4*)&Ks[kk][ty * 8];
            *(float4*)&a[4]  = *(float4*)&Ks[kk][ty * 8 + 4];
            *(float4*)&bv[0] = *(float4*)&Qs[kk][tx * 8];
            *(float4*)&bv[4] = *(float4*)&Qs[kk][tx * 8 + 4];
#pragma unroll
            for (int i = 0; i < 8; i++)
#pragma unroll
                for (int j = 0; j < 8; j++) acc[i][j] += a[i] * bv[j];
        }
    }
#pragma unroll
    for (int i = 0; i < 8; i++) {
        float* op = g_sim + ((size_t)b * Cc + c0 + ty * 8 + i) * Cc + d0 + tx * 8;
        *(float4*)op       = *(float4*)&acc[i][0];
        *(float4*)(op + 4) = *(float4*)&acc[i][4];
    }
}

// ---------------------------------------------------------------------------
// aff' = alpha * softmax_d(-sim) * s[b,d]   (fused gate + alpha), in place
// ---------------------------------------------------------------------------
__global__ void softmax_kernel(const float* __restrict__ alpha) {
    int row = blockIdx.x;          // b*Cc + c
    int b = row >> 8;
    float* p = g_sim + (size_t)row * Cc;
    int t = threadIdx.x;
    float v = -p[t];
    __shared__ float sm[8];
    __shared__ float ss[8];
    float wm = warpMax(v);
    if ((t & 31) == 0) sm[t >> 5] = wm;
    __syncthreads();
    float bm = sm[0];
#pragma unroll
    for (int i = 1; i < 8; i++) bm = fmaxf(bm, sm[i]);
    float e = expf(v - bm);
    float ws = warpSum(e);
    if ((t & 31) == 0) ss[t >> 5] = ws;
    __syncthreads();
    float tot = 0.f;
#pragma unroll
    for (int i = 0; i < 8; i++) tot += ss[i];
    p[t] = (e / tot) * alpha[0] * g_s[b * Cc + t];
}

// ---------------------------------------------------------------------------
// out[b,c,n] = sum_d aff'[b,c,d]*x[b,d,n] + x[b,c,n]
// M=256,N=4096,K=256. cp.async 4-stage; A [m][k] stride 20, B [k][n] stride 136.
// ---------------------------------------------------------------------------
#define GO_AS 2560    // 128*20
#define GO_BS 2176    // 16*136
#define GO_PIPE 4

__global__ __launch_bounds__(256, 2) void gemm_out_tc(
    const float* __restrict__ x, float* __restrict__ out) {
    extern __shared__ float smem[];
    float* Abuf = smem;
    float* Bbuf = smem + GO_PIPE * GO_AS;

    const int b = blockIdx.z;
    const int m0 = blockIdx.y * 128;
    const int n0 = blockIdx.x * 128;
    const int tid = threadIdx.x;
    const int lane = tid & 31, warp = tid >> 5;
    const int wm = (warp >> 2) * 64, wn = (warp & 3) * 32;
    const int g = lane >> 2, t4 = lane & 3;

    // A cp.async mapping (rows of aff, k-contiguous)
    const int r = tid >> 2;
    const int q = tid & 3;
    const float* gA0 = g_sim + ((size_t)b * Cc + m0 + r) * Cc + q * 4;
    const float* gA1 = gA0 + (size_t)64 * Cc;
    float* sA0 = Abuf + r * 20 + q * 4;
    float* sA1 = sA0 + 64 * 20;
    // B cp.async mapping (rows d of x, n-contiguous)
    const int d = tid >> 5;          // 0..7 (and +8)
    const int nc = (tid & 31) << 2;  // n offset 0..124
    const float* gB0 = x + ((size_t)b * Cc + d) * Nn + n0 + nc;
    const float* gB1 = gB0 + (size_t)8 * Nn;
    float* sB0 = Bbuf + d * 136 + nc;
    float* sB1 = sB0 + 8 * 136;

    const int NC = Cc / 16;  // 16

#pragma unroll
    for (int s = 0; s < GO_PIPE - 1; s++) {
        cp16(sA0 + s * GO_AS, gA0 + s * 16);
        cp16(sA1 + s * GO_AS, gA1 + s * 16);
        cp16(sB0 + s * GO_BS, gB0 + (size_t)s * 16 * Nn);
        cp16(sB1 + s * GO_BS, gB1 + (size_t)s * 16 * Nn);
        CP_COMMIT();
    }

    float acc[4][4][4];
#pragma unroll
    for (int i = 0; i < 4; i++)
#pragma unroll
        for (int j = 0; j < 4; j++)
#pragma unroll
            for (int rr = 0; rr < 4; rr++) acc[i][j][rr] = 0.f;

    for (int c = 0; c < NC; c++) {
        CP_WAIT2();
        __syncthreads();
        const uint32_t* Au = (const uint32_t*)(Abuf + (c % GO_PIPE) * GO_AS);
        const uint32_t* Bu = (const uint32_t*)(Bbuf + (c % GO_PIPE) * GO_BS);
#pragma unroll
        for (int ks = 0; ks < 2; ks++) {
            uint32_t af[4][4], bfr[4][2];
#pragma unroll
            for (int mi = 0; mi < 4; mi++) {
                int rw = wm + mi * 16 + g;
                int kk = ks * 8 + t4;
                af[mi][0] = Au[rw * 20 + kk];
                af[mi][1] = Au[(rw + 8) * 20 + kk];
                af[mi][2] = Au[rw * 20 + kk + 4];
                af[mi][3] = Au[(rw + 8) * 20 + kk + 4];
            }
#pragma unroll
            for (int ni = 0; ni < 4; ni++) {
                int cn = wn + ni * 8 + g;
                int kk = ks * 8 + t4;
                bfr[ni][0] = Bu[kk * 136 + cn];
                bfr[ni][1] = Bu[(kk + 4) * 136 + cn];
            }
#pragma unroll
            for (int mi = 0; mi < 4; mi++)
#pragma unroll
                for (int ni = 0; ni < 4; ni++)
                    mma_tf32(acc[mi][ni], af[mi], bfr[ni]);
        }
        int nx = c + GO_PIPE - 1;
        if (nx < NC) {
            int s = nx % GO_PIPE;
            cp16(sA0 + s * GO_AS, gA0 + nx * 16);
            cp16(sA1 + s * GO_AS, gA1 + nx * 16);
            cp16(sB0 + s * GO_BS, gB0 + (size_t)nx * 16 * Nn);
            cp16(sB1 + s * GO_BS, gB1 + (size_t)nx * 16 * Nn);
        }
        CP_COMMIT();
        __syncthreads();
    }

#pragma unroll
    for (int mi = 0; mi < 4; mi++) {
        int r0 = m0 + wm + mi * 16 + g;
        int r1 = r0 + 8;
#pragma unroll
        for (int ni = 0; ni < 4; ni++) {
            int cn = n0 + wn + ni * 8 + 2 * t4;
            size_t a0 = ((size_t)b * Cc + r0) * Nn + cn;
            size_t a1 = ((size_t)b * Cc + r1) * Nn + cn;
            float2 x0 = *(const float2*)(x + a0);
            float2 x1 = *(const float2*)(x + a1);
            float2 v0, v1;
            v0.x = acc[mi][ni][0] + x0.x;
            v0.y = acc[mi][ni][1] + x0.y;
            v1.x = acc[mi][ni][2] + x1.x;
            v1.y = acc[mi][ni][3] + x1.y;
            *(float2*)(out + a0) = v0;
            *(float2*)(out + a1) = v1;
        }
    }
}

// ---------------------------------------------------------------------------
extern "C" void kernel_launch(void* const* d_in, const int* in_sizes, int n_in,
                              void* d_out, int out_size) {
    const float* x    = (const float*)d_in[0];
    const float* Wq   = (const float*)d_in[1];
    const float* bn1g = (const float*)d_in[2];
    const float* bn1b = (const float*)d_in[3];
    const float* bn1m = (const float*)d_in[4];
    const float* bn1v = (const float*)d_in[5];
    const float* Wk   = (const float*)d_in[6];
    const float* bn2g = (const float*)d_in[7];
    const float* bn2b = (const float*)d_in[8];
    const float* bn2m = (const float*)d_in[9];
    const float* bn2v = (const float*)d_in[10];
    const float* W1   = (const float*)d_in[11];
    const float* W2   = (const float*)d_in[12];
    const float* alpha = (const float*)d_in[13];
    float* out = (float*)d_out;

    static_assert(2 * QK_PIPE * QK_AS * 4 == 81920, "qk smem");
    const int qk_smem = 2 * QK_PIPE * QK_AS * 4;            // 80 KB
    const int go_smem = GO_PIPE * (GO_AS + GO_BS) * 4;      // 74 KB
    cudaFuncSetAttribute(gemm_qk_tc, cudaFuncAttributeMaxDynamicSharedMemorySize, qk_smem);
    cudaFuncSetAttribute(gemm_out_tc, cudaFuncAttributeMaxDynamicSharedMemorySize, go_smem);

    pool_kernel<<<Bb * Cc, 256>>>(x);
    se_kernel<<<Bb, 256>>>(W1, W2);

    dim3 g1(Cc / 128, N8 / 128, 2 * Bb);
    gemm_qk_tc<<<g1, 256, qk_smem>>>(Wq, Wk, x,
                                     bn1g, bn1b, bn1m, bn1v,
                                     bn2g, bn2b, bn2m, bn2v);

    dim3 g2(Cc / 128, Cc / 128, Bb);
    gemm_sim_kernel<<<g2, 256>>>();

    softmax_kernel<<<Bb * Cc, 256>>>(alpha);

    dim3 g3(Nn / 128, Cc / 128, Bb);
    gemm_out_tc<<<g3, 256, go_smem>>>(x, out);
}

// round 5
// speedup vs baseline: 5.0073x; 1.6324x over previous
#include <cuda_runtime.h>
#include <cuda_fp16.h>
#include <cstdint>

#define Bb 32
#define Cc 256
#define Nn 4096
#define N8 512
#define EPSf 1e-5f

// Scratch (device globals — no allocation allowed)
__device__ float g_q[(size_t)Bb * N8 * Cc];
__device__ float g_k[(size_t)Bb * N8 * Cc];
__device__ float g_sim[(size_t)Bb * Cc * Cc];   // becomes alpha*aff*s in-place
__device__ float g_pooled[Bb * Cc];
__device__ float g_s[Bb * Cc];
__device__ __half g_xh[(size_t)Bb * Cc * Nn];   // fp16 copy of x
__device__ __half g_Wqh[(size_t)N8 * Nn];
__device__ __half g_Wkh[(size_t)N8 * Nn];

__device__ __forceinline__ float warpMax(float v) {
#pragma unroll
    for (int o = 16; o; o >>= 1) v = fmaxf(v, __shfl_xor_sync(0xffffffffu, v, o));
    return v;
}
__device__ __forceinline__ float warpSum(float v) {
#pragma unroll
    for (int o = 16; o; o >>= 1) v += __shfl_xor_sync(0xffffffffu, v, o);
    return v;
}

__device__ __forceinline__ void mma_tf32(float* c, const uint32_t* a, const uint32_t* b) {
    asm volatile(
        "mma.sync.aligned.m16n8k8.row.col.f32.tf32.tf32.f32 "
        "{%0,%1,%2,%3}, {%4,%5,%6,%7}, {%8,%9}, {%0,%1,%2,%3};\n"
        : "+f"(c[0]), "+f"(c[1]), "+f"(c[2]), "+f"(c[3])
        : "r"(a[0]), "r"(a[1]), "r"(a[2]), "r"(a[3]), "r"(b[0]), "r"(b[1]));
}
__device__ __forceinline__ void mma_f16(float* c, const uint32_t* a, const uint32_t* b) {
    asm volatile(
        "mma.sync.aligned.m16n8k16.row.col.f32.f16.f16.f32 "
        "{%0,%1,%2,%3}, {%4,%5,%6,%7}, {%8,%9}, {%0,%1,%2,%3};\n"
        : "+f"(c[0]), "+f"(c[1]), "+f"(c[2]), "+f"(c[3])
        : "r"(a[0]), "r"(a[1]), "r"(a[2]), "r"(a[3]), "r"(b[0]), "r"(b[1]));
}
#define LDSM_X4(r0, r1, r2, r3, addr) \
    asm volatile("ldmatrix.sync.aligned.m8n8.x4.shared.b16 {%0,%1,%2,%3}, [%4];" \
                 : "=r"(r0), "=r"(r1), "=r"(r2), "=r"(r3) : "r"(addr))

__device__ __forceinline__ void cp16(void* s, const void* g) {
    uint32_t sa = (uint32_t)__cvta_generic_to_shared(s);
    asm volatile("cp.async.cg.shared.global [%0], [%1], 16;" :: "r"(sa), "l"(g));
}
__device__ __forceinline__ void cp16s(uint32_t saddr, const void* g) {
    asm volatile("cp.async.cg.shared.global [%0], [%1], 16;" :: "r"(saddr), "l"(g));
}
#define CP_COMMIT() asm volatile("cp.async.commit_group;")
#define CP_WAIT2()  asm volatile("cp.async.wait_group 2;")

__device__ __forceinline__ uint32_t smem_u32(const void* p) {
    return (uint32_t)__cvta_generic_to_shared(p);
}

// ---------------------------------------------------------------------------
// pooled[b,c] = max_n x[b,c,n]; also writes fp16 copy of x.
// ---------------------------------------------------------------------------
__global__ void pool_kernel(const float* __restrict__ x) {
    int row = blockIdx.x;  // b*Cc + c
    const float4* xr = (const float4*)(x + (size_t)row * Nn);
    uint2* xh = (uint2*)(g_xh + (size_t)row * Nn);
    float m = -3.0e38f;
    for (int i = threadIdx.x; i < Nn / 4; i += 256) {
        float4 v = xr[i];
        __half2 p01 = __floats2half2_rn(v.x, v.y);
        __half2 p23 = __floats2half2_rn(v.z, v.w);
        uint2 u;
        u.x = *reinterpret_cast<uint32_t*>(&p01);
        u.y = *reinterpret_cast<uint32_t*>(&p23);
        xh[i] = u;
        m = fmaxf(m, fmaxf(fmaxf(v.x, v.y), fmaxf(v.z, v.w)));
    }
    m = warpMax(m);
    __shared__ float sm[8];
    if ((threadIdx.x & 31) == 0) sm[threadIdx.x >> 5] = m;
    __syncthreads();
    if (threadIdx.x == 0) {
        float r = sm[0];
#pragma unroll
        for (int i = 1; i < 8; i++) r = fmaxf(r, sm[i]);
        g_pooled[row] = r;
    }
}

// ---------------------------------------------------------------------------
// Convert Wq, Wk to fp16. One thread = one float4 of each.
// ---------------------------------------------------------------------------
__global__ void convW_kernel(const float* __restrict__ Wq, const float* __restrict__ Wk) {
    int i = blockIdx.x * 256 + threadIdx.x;   // 512*4096/4 = 524288 float4s
    float4 q = ((const float4*)Wq)[i];
    float4 k = ((const float4*)Wk)[i];
    __half2 q01 = __floats2half2_rn(q.x, q.y), q23 = __floats2half2_rn(q.z, q.w);
    __half2 k01 = __floats2half2_rn(k.x, k.y), k23 = __floats2half2_rn(k.z, k.w);
    uint2 uq, uk;
    uq.x = *reinterpret_cast<uint32_t*>(&q01); uq.y = *reinterpret_cast<uint32_t*>(&q23);
    uk.x = *reinterpret_cast<uint32_t*>(&k01); uk.y = *reinterpret_cast<uint32_t*>(&k23);
    ((uint2*)g_Wqh)[i] = uq;
    ((uint2*)g_Wkh)[i] = uk;
}

// ---------------------------------------------------------------------------
__global__ void se_kernel(const float* __restrict__ W1, const float* __restrict__ W2) {
    int b = blockIdx.x;
    int t = threadIdx.x;
    __shared__ float h[32];
    if (t < 32) {
        float acc = 0.f;
        const float* w = W1 + t * Cc;
        const float* p = g_pooled + b * Cc;
        for (int c = 0; c < Cc; c++) acc += w[c] * p[c];
        h[t] = fmaxf(acc, 0.f);
    }
    __syncthreads();
    float acc = 0.f;
    const float* w2 = W2 + t * 32;
#pragma unroll
    for (int j = 0; j < 32; j++) acc += w2[j] * h[j];
    g_s[b * Cc + t] = 1.f / (1.f + expf(-acc));
}

// ---------------------------------------------------------------------------
// fp16 tensor-core q/k GEMM: out[b,q,c] = relu(BN( sum_n W[q,n]*x[b,c,n] ))
// M=512,N=256,K=4096 per (b,sel). Block 128x128, kc=32 halves, 4-stage cp.async.
// Smem row = 40 halves (80B) -> conflict-free ldmatrix. 8 warps, 64x32 tiles.
// ---------------------------------------------------------------------------
#define QK_ROWB 80          // bytes per smem row
#define QK_OPB  10240       // bytes per operand per stage (128*80)
#define QK_STB  20480       // bytes per stage (A+B)
#define QK_NCH  (Nn / 32)   // 128 chunks

__global__ __launch_bounds__(256, 2) void gemm_qk_f16(
    const float* __restrict__ gq, const float* __restrict__ bq,
    const float* __restrict__ mq, const float* __restrict__ vq,
    const float* __restrict__ gk, const float* __restrict__ bk,
    const float* __restrict__ mk, const float* __restrict__ vk) {
    extern __shared__ char rawsm[];
    const uint32_t sbase = smem_u32(rawsm);

    const int z = blockIdx.z;
    const int b = z >> 1;
    const int sel = z & 1;
    const int m0 = blockIdx.y * 128;
    const int n0 = blockIdx.x * 128;
    const int tid = threadIdx.x;
    const int lane = tid & 31, warp = tid >> 5;
    const int wm = (warp >> 2) * 64, wn = (warp & 3) * 32;
    const int g = lane >> 2, t4 = lane & 3;

    // cp.async mapping: thread -> (row, 32B half-row)
    const int lrow = tid >> 1;
    const int lhalf = tid & 1;
    const __half* gW = (sel ? g_Wkh : g_Wqh) + (size_t)(m0 + lrow) * Nn + lhalf * 16;
    const __half* gX = g_xh + ((size_t)b * Cc + n0 + lrow) * Nn + lhalf * 16;
    const uint32_t sA = sbase + lrow * QK_ROWB + lhalf * 32;
    const uint32_t sB = sA + QK_OPB;

    // ldmatrix lane addressing
    const uint32_t aoff = (uint32_t)((wm + (lane & 7) + ((lane >> 3) & 1) * 8) * QK_ROWB
                                     + ((lane >> 4) & 1) * 16);
    const uint32_t boff = (uint32_t)((wn + (lane & 7) + ((lane >> 4) & 1) * 8) * QK_ROWB
                                     + ((lane >> 3) & 1) * 16);

    // prologue: 3 stages
#pragma unroll
    for (int s = 0; s < 3; s++) {
        uint32_t st = s * QK_STB;
        int koff = s * 32;
        cp16s(sA + st,      gW + koff);
        cp16s(sA + st + 16, gW + koff + 8);
        cp16s(sB + st,      gX + koff);
        cp16s(sB + st + 16, gX + koff + 8);
        CP_COMMIT();
    }

    float acc[4][4][4];
#pragma unroll
    for (int i = 0; i < 4; i++)
#pragma unroll
        for (int j = 0; j < 4; j++)
#pragma unroll
            for (int r = 0; r < 4; r++) acc[i][j][r] = 0.f;

    for (int c = 0; c < QK_NCH; c++) {
        CP_WAIT2();
        __syncthreads();
        const uint32_t st = (c & 3) * QK_STB;
        const uint32_t Ab = sbase + st;
        const uint32_t Bbp = Ab + QK_OPB;
#pragma unroll
        for (int ks = 0; ks < 2; ks++) {
            uint32_t af[4][4], bfr[4][2];
#pragma unroll
            for (int mi = 0; mi < 4; mi++)
                LDSM_X4(af[mi][0], af[mi][1], af[mi][2], af[mi][3],
                        Ab + aoff + mi * (16 * QK_ROWB) + ks * 32);
#pragma unroll
            for (int nj = 0; nj < 2; nj++) {
                uint32_t r0, r1, r2, r3;
                LDSM_X4(r0, r1, r2, r3, Bbp + boff + nj * (16 * QK_ROWB) + ks * 32);
                bfr[2 * nj][0] = r0; bfr[2 * nj][1] = r1;
                bfr[2 * nj + 1][0] = r2; bfr[2 * nj + 1][1] = r3;
            }
#pragma unroll
            for (int mi = 0; mi < 4; mi++)
#pragma unroll
                for (int ni = 0; ni < 4; ni++)
                    mma_f16(acc[mi][ni], af[mi], bfr[ni]);
        }
        int nx = c + 3;
        if (nx < QK_NCH) {
            uint32_t s2 = (nx & 3) * QK_STB;
            int koff = nx * 32;
            cp16s(sA + s2,      gW + koff);
            cp16s(sA + s2 + 16, gW + koff + 8);
            cp16s(sB + s2,      gX + koff);
            cp16s(sB + s2 + 16, gX + koff + 8);
        }
        CP_COMMIT();
        __syncthreads();
    }

    const float* gg  = sel ? gk : gq;
    const float* bbp = sel ? bk : bq;
    const float* mmp = sel ? mk : mq;
    const float* vvp = sel ? vk : vq;
    float* outp = sel ? g_k : g_q;
#pragma unroll
    for (int mi = 0; mi < 4; mi++) {
        int r0 = m0 + wm + mi * 16 + g;
        int r1 = r0 + 8;
        float sc0 = gg[r0] * rsqrtf(vvp[r0] + EPSf);
        float sh0 = bbp[r0] - mmp[r0] * sc0;
        float sc1 = gg[r1] * rsqrtf(vvp[r1] + EPSf);
        float sh1 = bbp[r1] - mmp[r1] * sc1;
#pragma unroll
        for (int ni = 0; ni < 4; ni++) {
            int cn = n0 + wn + ni * 8 + 2 * t4;
            float2 v0, v1;
            v0.x = fmaxf(acc[mi][ni][0] * sc0 + sh0, 0.f);
            v0.y = fmaxf(acc[mi][ni][1] * sc0 + sh0, 0.f);
            v1.x = fmaxf(acc[mi][ni][2] * sc1 + sh1, 0.f);
            v1.y = fmaxf(acc[mi][ni][3] * sc1 + sh1, 0.f);
            *(float2*)&outp[((size_t)b * N8 + r0) * Cc + cn] = v0;
            *(float2*)&outp[((size_t)b * N8 + r1) * Cc + cn] = v1;
        }
    }
}

// ---------------------------------------------------------------------------
// sim[b,c,d] = sum_kk k[b,kk,c]*q[b,kk,d] -- tf32 mma.sync, M=N=256, K=512.
// Both operands staged as [k][136] (m/n contiguous rows).
// ---------------------------------------------------------------------------
#define SIM_TS 2176
#define SIM_PIPE 4

__global__ __launch_bounds__(256, 2) void gemm_sim_tc(void) {
    extern __shared__ float smem[];
    float* Abuf = smem;
    float* Bbuf = smem + SIM_PIPE * SIM_TS;

    const int b = blockIdx.z;
    const int c0 = blockIdx.y * 128;
    const int d0 = blockIdx.x * 128;
    const int tid = threadIdx.x;
    const int lane = tid & 31, warp = tid >> 5;
    const int wm = (warp >> 2) * 64, wn = (warp & 3) * 32;
    const int g = lane >> 2, t4 = lane & 3;

    const int sd = tid >> 5;
    const int snq = (tid & 31) << 2;
    const float* gA0 = g_k + ((size_t)b * N8 + sd) * Cc + c0 + snq;
    const float* gA1 = gA0 + (size_t)8 * Cc;
    const float* gB0 = g_q + ((size_t)b * N8 + sd) * Cc + d0 + snq;
    const float* gB1 = gB0 + (size_t)8 * Cc;
    float* sA0 = Abuf + sd * 136 + snq;
    float* sA1 = sA0 + 8 * 136;
    float* sB0 = Bbuf + sd * 136 + snq;
    float* sB1 = sB0 + 8 * 136;

    const int NC = N8 / 16;  // 32

#pragma unroll
    for (int s = 0; s < SIM_PIPE - 1; s++) {
        cp16(sA0 + s * SIM_TS, gA0 + (size_t)s * 16 * Cc);
        cp16(sA1 + s * SIM_TS, gA1 + (size_t)s * 16 * Cc);
        cp16(sB0 + s * SIM_TS, gB0 + (size_t)s * 16 * Cc);
        cp16(sB1 + s * SIM_TS, gB1 + (size_t)s * 16 * Cc);
        CP_COMMIT();
    }

    float acc[4][4][4];
#pragma unroll
    for (int i = 0; i < 4; i++)
#pragma unroll
        for (int j = 0; j < 4; j++)
#pragma unroll
            for (int rr = 0; rr < 4; rr++) acc[i][j][rr] = 0.f;

    for (int c = 0; c < NC; c++) {
        CP_WAIT2();
        __syncthreads();
        const uint32_t* Au = (const uint32_t*)(Abuf + (c % SIM_PIPE) * SIM_TS);
        const uint32_t* Bu = (const uint32_t*)(Bbuf + (c % SIM_PIPE) * SIM_TS);
#pragma unroll
        for (int ks = 0; ks < 2; ks++) {
            uint32_t af[4][4], bfr[4][2];
            int kk = ks * 8 + t4;
#pragma unroll
            for (int mi = 0; mi < 4; mi++) {
                int rw = wm + mi * 16 + g;
                af[mi][0] = Au[kk * 136 + rw];
                af[mi][1] = Au[kk * 136 + rw + 8];
                af[mi][2] = Au[(kk + 4) * 136 + rw];
                af[mi][3] = Au[(kk + 4) * 136 + rw + 8];
            }
#pragma unroll
            for (int ni = 0; ni < 4; ni++) {
                int cn = wn + ni * 8 + g;
                bfr[ni][0] = Bu[kk * 136 + cn];
                bfr[ni][1] = Bu[(kk + 4) * 136 + cn];
            }
#pragma unroll
            for (int mi = 0; mi < 4; mi++)
#pragma unroll
                for (int ni = 0; ni < 4; ni++)
                    mma_tf32(acc[mi][ni], af[mi], bfr[ni]);
        }
        int nx = c + SIM_PIPE - 1;
        if (nx < NC) {
            int s = nx % SIM_PIPE;
            cp16(sA0 + s * SIM_TS, gA0 + (size_t)nx * 16 * Cc);
            cp16(sA1 + s * SIM_TS, gA1 + (size_t)nx * 16 * Cc);
            cp16(sB0 + s * SIM_TS, gB0 + (size_t)nx * 16 * Cc);
            cp16(sB1 + s * SIM_TS, gB1 + (size_t)nx * 16 * Cc);
        }
        CP_COMMIT();
        __syncthreads();
    }

#pragma unroll
    for (int mi = 0; mi < 4; mi++) {
        int r0 = c0 + wm + mi * 16 + g;
        int r1 = r0 + 8;
#pragma unroll
        for (int ni = 0; ni < 4; ni++) {
            int cn = d0 + wn + ni * 8 + 2 * t4;
            float* p0 = g_sim + ((size_t)b * Cc + r0) * Cc + cn;
            float* p1 = g_sim + ((size_t)b * Cc + r1) * Cc + cn;
            *(float2*)p0 = make_float2(acc[mi][ni][0], acc[mi][ni][1]);
            *(float2*)p1 = make_float2(acc[mi][ni][2], acc[mi][ni][3]);
        }
    }
}

// ---------------------------------------------------------------------------
// aff' = alpha * softmax_d(-sim) * s[b,d], in place
// ---------------------------------------------------------------------------
__global__ void softmax_kernel(const float* __restrict__ alpha) {
    int row = blockIdx.x;
    int b = row >> 8;
    float* p = g_sim + (size_t)row * Cc;
    int t = threadIdx.x;
    float v = -p[t];
    __shared__ float sm[8];
    __shared__ float ss[8];
    float wm = warpMax(v);
    if ((t & 31) == 0) sm[t >> 5] = wm;
    __syncthreads();
    float bm = sm[0];
#pragma unroll
    for (int i = 1; i < 8; i++) bm = fmaxf(bm, sm[i]);
    float e = expf(v - bm);
    float ws = warpSum(e);
    if ((t & 31) == 0) ss[t >> 5] = ws;
    __syncthreads();
    float tot = 0.f;
#pragma unroll
    for (int i = 0; i < 8; i++) tot += ss[i];
    p[t] = (e / tot) * alpha[0] * g_s[b * Cc + t];
}

// ---------------------------------------------------------------------------
// out[b,c,n] = sum_d aff'[b,c,d]*x[b,d,n] + x[b,c,n]   (tf32 mma.sync)
// ---------------------------------------------------------------------------
#define GO_AS 2560
#define GO_BS 2176
#define GO_PIPE 4

__global__ __launch_bounds__(256, 2) void gemm_out_tc(
    const float* __restrict__ x, float* __restrict__ out) {
    extern __shared__ float smem[];
    float* Abuf = smem;
    float* Bbuf = smem + GO_PIPE * GO_AS;

    const int b = blockIdx.z;
    const int m0 = blockIdx.y * 128;
    const int n0 = blockIdx.x * 128;
    const int tid = threadIdx.x;
    const int lane = tid & 31, warp = tid >> 5;
    const int wm = (warp >> 2) * 64, wn = (warp & 3) * 32;
    const int g = lane >> 2, t4 = lane & 3;

    const int r = tid >> 2;
    const int q = tid & 3;
    const float* gA0 = g_sim + ((size_t)b * Cc + m0 + r) * Cc + q * 4;
    const float* gA1 = gA0 + (size_t)64 * Cc;
    float* sA0 = Abuf + r * 20 + q * 4;
    float* sA1 = sA0 + 64 * 20;
    const int d = tid >> 5;
    const int nc = (tid & 31) << 2;
    const float* gB0 = x + ((size_t)b * Cc + d) * Nn + n0 + nc;
    const float* gB1 = gB0 + (size_t)8 * Nn;
    float* sB0 = Bbuf + d * 136 + nc;
    float* sB1 = sB0 + 8 * 136;

    const int NC = Cc / 16;

#pragma unroll
    for (int s = 0; s < GO_PIPE - 1; s++) {
        cp16(sA0 + s * GO_AS, gA0 + s * 16);
        cp16(sA1 + s * GO_AS, gA1 + s * 16);
        cp16(sB0 + s * GO_BS, gB0 + (size_t)s * 16 * Nn);
        cp16(sB1 + s * GO_BS, gB1 + (size_t)s * 16 * Nn);
        CP_COMMIT();
    }

    float acc[4][4][4];
#pragma unroll
    for (int i = 0; i < 4; i++)
#pragma unroll
        for (int j = 0; j < 4; j++)
#pragma unroll
            for (int rr = 0; rr < 4; rr++) acc[i][j][rr] = 0.f;

    for (int c = 0; c < NC; c++) {
        CP_WAIT2();
        __syncthreads();
        const uint32_t* Au = (const uint32_t*)(Abuf + (c % GO_PIPE) * GO_AS);
        const uint32_t* Bu = (const uint32_t*)(Bbuf + (c % GO_PIPE) * GO_BS);
#pragma unroll
        for (int ks = 0; ks < 2; ks++) {
            uint32_t af[4][4], bfr[4][2];
#pragma unroll
            for (int mi = 0; mi < 4; mi++) {
                int rw = wm + mi * 16 + g;
                int kk = ks * 8 + t4;
                af[mi][0] = Au[rw * 20 + kk];
                af[mi][1] = Au[(rw + 8) * 20 + kk];
                af[mi][2] = Au[rw * 20 + kk + 4];
                af[mi][3] = Au[(rw + 8) * 20 + kk + 4];
            }
#pragma unroll
            for (int ni = 0; ni < 4; ni++) {
                int cn = wn + ni * 8 + g;
                int kk = ks * 8 + t4;
                bfr[ni][0] = Bu[kk * 136 + cn];
                bfr[ni][1] = Bu[(kk + 4) * 136 + cn];
            }
#pragma unroll
            for (int mi = 0; mi < 4; mi++)
#pragma unroll
                for (int ni = 0; ni < 4; ni++)
                    mma_tf32(acc[mi][ni], af[mi], bfr[ni]);
        }
        int nx = c + GO_PIPE - 1;
        if (nx < NC) {
            int s = nx % GO_PIPE;
            cp16(sA0 + s * GO_AS, gA0 + nx * 16);
            cp16(sA1 + s * GO_AS, gA1 + nx * 16);
            cp16(sB0 + s * GO_BS, gB0 + (size_t)nx * 16 * Nn);
            cp16(sB1 + s * GO_BS, gB1 + (size_t)nx * 16 * Nn);
        }
        CP_COMMIT();
        __syncthreads();
    }

#pragma unroll
    for (int mi = 0; mi < 4; mi++) {
        int r0 = m0 + wm + mi * 16 + g;
        int r1 = r0 + 8;
#pragma unroll
        for (int ni = 0; ni < 4; ni++) {
            int cn = n0 + wn + ni * 8 + 2 * t4;
            size_t a0 = ((size_t)b * Cc + r0) * Nn + cn;
            size_t a1 = ((size_t)b * Cc + r1) * Nn + cn;
            float2 x0 = *(const float2*)(x + a0);
            float2 x1 = *(const float2*)(x + a1);
            *(float2*)(out + a0) = make_float2(acc[mi][ni][0] + x0.x, acc[mi][ni][1] + x0.y);
            *(float2*)(out + a1) = make_float2(acc[mi][ni][2] + x1.x, acc[mi][ni][3] + x1.y);
        }
    }
}

// ---------------------------------------------------------------------------
extern "C" void kernel_launch(void* const* d_in, const int* in_sizes, int n_in,
                              void* d_out, int out_size) {
    const float* x    = (const float*)d_in[0];
    const float* Wq   = (const float*)d_in[1];
    const float* bn1g = (const float*)d_in[2];
    const float* bn1b = (const float*)d_in[3];
    const float* bn1m = (const float*)d_in[4];
    const float* bn1v = (const float*)d_in[5];
    const float* Wk   = (const float*)d_in[6];
    const float* bn2g = (const float*)d_in[7];
    const float* bn2b = (const float*)d_in[8];
    const float* bn2m = (const float*)d_in[9];
    const float* bn2v = (const float*)d_in[10];
    const float* W1   = (const float*)d_in[11];
    const float* W2   = (const float*)d_in[12];
    const float* alpha = (const float*)d_in[13];
    float* out = (float*)d_out;

    const int qk_smem = 4 * QK_STB;                          // 81920 B
    const int sim_smem = 2 * SIM_PIPE * SIM_TS * 4;          // 69632 B
    const int go_smem = GO_PIPE * (GO_AS + GO_BS) * 4;       // 75776 B
    cudaFuncSetAttribute(gemm_qk_f16, cudaFuncAttributeMaxDynamicSharedMemorySize, qk_smem);
    cudaFuncSetAttribute(gemm_sim_tc, cudaFuncAttributeMaxDynamicSharedMemorySize, sim_smem);
    cudaFuncSetAttribute(gemm_out_tc, cudaFuncAttributeMaxDynamicSharedMemorySize, go_smem);

    convW_kernel<<<(N8 * Nn / 4) / 256, 256>>>(Wq, Wk);
    pool_kernel<<<Bb * Cc, 256>>>(x);
    se_kernel<<<Bb, 256>>>(W1, W2);

    dim3 g1(Cc / 128, N8 / 128, 2 * Bb);
    gemm_qk_f16<<<g1, 256, qk_smem>>>(bn1g, bn1b, bn1m, bn1v,
                                      bn2g, bn2b, bn2m, bn2v);

    dim3 g2(Cc / 128, Cc / 128, Bb);
    gemm_sim_tc<<<g2, 256, sim_smem>>>();

    softmax_kernel<<<Bb * Cc, 256>>>(alpha);

    dim3 g3(Nn / 128, Cc / 128, Bb);
    gemm_out_tc<<<g3, 256, go_smem>>>(x, out);
}